// round 13
// baseline (speedup 1.0000x reference)
#include <cuda_runtime.h>
#include <cuda_bf16.h>

// SepConv: out[b,c,i,j] = sum_{u,v} img[b,c,i+u,j+v] * vert[b,u,i,j] * hori[b,v,i,j]
// Shapes: img[8,3,512,512], hori[8,13,500,500], vert[8,13,500,500], out[8,3,500,500]
// Factorized: out = sum_u vert[u] * (sum_v hori[v] * img[i+u, j+v])
// R10: R9 (best: 85.8us) + 3-deep vert prefetch ring. vert streams from DRAM
//   (lat ~577cy); distance-1 prefetch (~250cy) left ~300cy exposed per u.
//   Distance-3 (~750cy) covers it. +8 regs, everything else untouched.

#define KSZ 13
#define CC  3
#define WW  512
#define HH  512
#define WO  500
#define HO  500

#define TX  32                 // thread-groups in j; each thread covers 4 j
#define TY  8                  // output rows per block
#define JBLK (TX * 4)          // 128 output columns per block
#define TILE_ROWS (TY + KSZ - 1)   // 20 img rows
#define TILE_Q   36                // float4 per tile row (144 floats)

__global__ __launch_bounds__(TX * TY, 2)
void sepconv_kernel(const float* __restrict__ img,
                    const float* __restrict__ hori,
                    const float* __restrict__ vert,
                    float* __restrict__ out) {
    __shared__ float4 s[CC][TILE_ROWS][TILE_Q];

    const int b  = blockIdx.z;
    const int j0 = blockIdx.x * JBLK;
    const int i0 = blockIdx.y * TY;
    const int tx = threadIdx.x, ty = threadIdx.y;
    const int tid = ty * TX + tx;

    const int i = i0 + ty;
    const int j = j0 + 4 * tx;
    const bool active = (i < WO) && (j < HO);    // HO%4==0 -> float4 valid when j<HO
    // clamped coords so edge threads issue harmless in-bounds loads
    const int ic = (i < WO) ? i : (WO - 1);
    const int jc = (j < HO) ? j : (HO - 4);

    // ---- weight loads FIRST: independent of smem, overlap the tile load ----
    float4 hw[KSZ];
    const float* hbase = hori + (((size_t)b * KSZ) * WO + ic) * HO + jc;
    #pragma unroll
    for (int v = 0; v < KSZ; v++)
        hw[v] = *(const float4*)(hbase + (size_t)v * WO * HO);

    const float* vbase = vert + (((size_t)b * KSZ) * WO + ic) * HO + jc;
    // 3-deep vert prefetch ring (distance covers DRAM latency)
    float4 vbuf[3];
    #pragma unroll
    for (int p = 0; p < 3; p++)
        vbuf[p] = *(const float4*)(vbase + (size_t)p * WO * HO);

    // ---- cooperative load of the img tile (3 channels, 20 rows, 144 cols) ----
    const int NQ = CC * TILE_ROWS * TILE_Q;   // 2160 float4
    for (int f = tid; f < NQ; f += TX * TY) {
        int c   = f / (TILE_ROWS * TILE_Q);
        int rem = f - c * (TILE_ROWS * TILE_Q);
        int r   = rem / TILE_Q;
        int q   = rem - r * TILE_Q;
        int gx  = i0 + r; if (gx > WW - 1) gx = WW - 1;   // clamped rows feed only invalid outs
        int gy  = j0 + 4 * q;
        const float* base = img + (((size_t)b * CC + c) * WW + gx) * HH;
        float4 val;
        if (gy + 3 <= HH - 1) {
            val = *(const float4*)(base + gy);
        } else {
            int y0 = gy     < HH ? gy     : HH - 1;
            int y1 = gy + 1 < HH ? gy + 1 : HH - 1;
            int y2 = gy + 2 < HH ? gy + 2 : HH - 1;
            int y3 = gy + 3 < HH ? gy + 3 : HH - 1;
            val = make_float4(base[y0], base[y1], base[y2], base[y3]);
        }
        s[c][r][q] = val;
    }
    __syncthreads();

    if (!active) return;   // no further barriers below

    float4 acc[CC];
    #pragma unroll
    for (int c = 0; c < CC; c++) acc[c] = make_float4(0.f, 0.f, 0.f, 0.f);

    #pragma unroll
    for (int u = 0; u < KSZ; u++) {
        float4 vw = vbuf[u % 3];                     // static after unroll
        if (u + 3 < KSZ)
            vbuf[u % 3] = *(const float4*)(vbase + (size_t)(u + 3) * WO * HO);

        #pragma unroll
        for (int c = 0; c < CC; c++) {
            // 16-float register window covering columns j .. j+15 of img row i+u
            const float4* row4 = &s[c][ty + u][0] + tx;
            float w[16];
            #pragma unroll
            for (int k = 0; k < 4; k++) {
                float4 t4 = row4[k];
                w[4*k+0] = t4.x; w[4*k+1] = t4.y; w[4*k+2] = t4.z; w[4*k+3] = t4.w;
            }
            float r0 = 0.f, r1 = 0.f, r2 = 0.f, r3 = 0.f;
            #pragma unroll
            for (int v = 0; v < KSZ; v++) {
                r0 = fmaf(hw[v].x, w[v + 0], r0);
                r1 = fmaf(hw[v].y, w[v + 1], r1);
                r2 = fmaf(hw[v].z, w[v + 2], r2);
                r3 = fmaf(hw[v].w, w[v + 3], r3);
            }
            acc[c].x = fmaf(vw.x, r0, acc[c].x);
            acc[c].y = fmaf(vw.y, r1, acc[c].y);
            acc[c].z = fmaf(vw.z, r2, acc[c].z);
            acc[c].w = fmaf(vw.w, r3, acc[c].w);
        }
    }

    #pragma unroll
    for (int c = 0; c < CC; c++) {
        float* obase = out + (((size_t)b * CC + c) * WO + i) * HO + j;
        *(float4*)obase = acc[c];
    }
}

extern "C" void kernel_launch(void* const* d_in, const int* in_sizes, int n_in,
                              void* d_out, int out_size) {
    const float* img  = (const float*)d_in[0];
    const float* hori = (const float*)d_in[1];
    const float* vert = (const float*)d_in[2];
    float* out = (float*)d_out;

    const int B = 8;
    dim3 block(TX, TY);                     // 256 threads
    dim3 grid((HO + JBLK - 1) / JBLK,       // 4
              (WO + TY - 1) / TY,           // 63
              B);                           // 8 -> 2016 blocks
    sepconv_kernel<<<grid, block>>>(img, hori, vert, out);
}